// round 11
// baseline (speedup 1.0000x reference)
#include <cuda_runtime.h>

#define HW 3136

__device__ float g_pooled[32 * 256];

// ---------------- K1: global average pool (4 planes / block, 8-deep load batches) ----------------
__global__ void __launch_bounds__(256) pool_kernel(const float* __restrict__ x) {
    const int plane0 = blockIdx.x * 4;
    const float4* xp = reinterpret_cast<const float4*>(x + (size_t)plane0 * HW);
    const int tid = threadIdx.x;
    float s0 = 0.f, s1 = 0.f, s2 = 0.f, s3 = 0.f;

    {
        float4 a0 = xp[tid],        b0 = xp[tid + 784],
               c0 = xp[tid + 1568], d0 = xp[tid + 2352];
        float4 a1 = xp[tid + 256],  b1 = xp[tid + 1040],
               c1 = xp[tid + 1824], d1 = xp[tid + 2608];
        s0 = (a0.x + a0.y) + (a0.z + a0.w) + (a1.x + a1.y) + (a1.z + a1.w);
        s1 = (b0.x + b0.y) + (b0.z + b0.w) + (b1.x + b1.y) + (b1.z + b1.w);
        s2 = (c0.x + c0.y) + (c0.z + c0.w) + (c1.x + c1.y) + (c1.z + c1.w);
        s3 = (d0.x + d0.y) + (d0.z + d0.w) + (d1.x + d1.y) + (d1.z + d1.w);
    }
    {
        float4 a = xp[tid + 512], b = xp[tid + 1296],
               c = xp[tid + 2080], d = xp[tid + 2864];
        s0 += (a.x + a.y) + (a.z + a.w);
        s1 += (b.x + b.y) + (b.z + b.w);
        s2 += (c.x + c.y) + (c.z + c.w);
        s3 += (d.x + d.y) + (d.z + d.w);
    }
    if (tid < 16) {
        float4 a = xp[tid + 768], b = xp[tid + 1552],
               c = xp[tid + 2336], d = xp[tid + 3120];
        s0 += (a.x + a.y) + (a.z + a.w);
        s1 += (b.x + b.y) + (b.z + b.w);
        s2 += (c.x + c.y) + (c.z + c.w);
        s3 += (d.x + d.y) + (d.z + d.w);
    }

    #pragma unroll
    for (int o = 16; o; o >>= 1) {
        s0 += __shfl_xor_sync(0xffffffffu, s0, o);
        s1 += __shfl_xor_sync(0xffffffffu, s1, o);
        s2 += __shfl_xor_sync(0xffffffffu, s2, o);
        s3 += __shfl_xor_sync(0xffffffffu, s3, o);
    }
    __shared__ float sh[8][4];
    if ((tid & 31) == 0) {
        const int w = tid >> 5;
        sh[w][0] = s0; sh[w][1] = s1; sh[w][2] = s2; sh[w][3] = s3;
    }
    __syncthreads();
    if (tid < 32) {
        const int pl = tid & 3;
        const int w  = tid >> 2;
        float v = (w < 8) ? sh[w][pl] : 0.f;
        v += __shfl_xor_sync(0xffffffffu, v, 16);
        v += __shfl_xor_sync(0xffffffffu, v, 8);
        v += __shfl_xor_sync(0xffffffffu, v, 4);
        if (w == 0) g_pooled[plane0 + pl] = v * (1.0f / 3136.f);
    }
}

// ---------------- K2 (PDL secondary): hoisted x loads -> grid-dep sync -> kgen -> conv ----------------
__global__ void __launch_bounds__(256) kconv_kernel(const float* __restrict__ x,
                                                    const float* __restrict__ Wk,
                                                    const float* __restrict__ bk,
                                                    float* __restrict__ out)
{
    __shared__ float psh[256];
    __shared__ float kern_s[18];

    const int bid  = blockIdx.x;             // forward order: chase pool's L2 footprint
    const int b    = bid >> 7;
    const int pair = bid & 127;
    const int tid  = threadIdx.x;
    const int warp = tid >> 5, lane = tid & 31;
    const int c0   = pair * 2;

    // ---- conv geometry: half-warp = (plane, row-group); cgp = lane&15 ----
    const int grp = (warp << 1) | (lane >> 4);
    const int pl  = grp & 1;
    const int rg  = grp >> 1;
    const int cgp = lane & 15;
    const bool act = cgp < 14;
    const int xc = cgp * 4;
    const int y0 = rg * 7;
    const bool lok = act && (cgp > 0);
    const bool rok = act && (cgp < 13);

    const size_t plane = (size_t)b * 256 + c0 + pl;
    const float* xp = x + plane * HW + xc;

    // ---- hoisted conv loads (independent of pool) — overlap with primary grid ----
    float4 R[9];
    const float4 z4 = make_float4(0.f, 0.f, 0.f, 0.f);
    R[0] = (act && rg > 0) ? __ldg(reinterpret_cast<const float4*>(xp + (y0 - 1) * 56)) : z4;
    #pragma unroll
    for (int j = 1; j < 8; j++)
        R[j] = act ? __ldg(reinterpret_cast<const float4*>(xp + (y0 - 1 + j) * 56)) : z4;
    R[8] = (act && rg < 7) ? __ldg(reinterpret_cast<const float4*>(xp + (y0 + 7) * 56)) : z4;

    // ---- wait for pool grid to complete (g_pooled visible) ----
    cudaGridDependencySynchronize();

    // ---- kgen: 18 rows over 8 warps ----
    psh[tid] = g_pooled[b * 256 + tid];
    __syncthreads();

    #pragma unroll
    for (int sl = 0; sl < 3; sl++) {
        if (sl == 2 && warp >= 2) break;
        const int r = (sl < 2) ? (2 * warp + sl) : (16 + warp);
        const int o = c0 * 9 + r;
        const float* wr = Wk + (size_t)o * 256;
        float a = 0.f;
        #pragma unroll
        for (int i = 0; i < 8; i++)
            a = fmaf(__ldg(wr + lane + 32 * i), psh[lane + 32 * i], a);
        #pragma unroll
        for (int off = 16; off; off >>= 1) a += __shfl_xor_sync(0xffffffffu, a, off);
        if (lane == 0) kern_s[r] = fmaxf(a + __ldg(bk + o), 0.f);
    }
    __syncthreads();

    const float* kp = kern_s + pl * 9;
    const float k0 = kp[0], k1 = kp[1], k2 = kp[2];
    const float k3 = kp[3], k4 = kp[4], k5 = kp[5];
    const float k6 = kp[6], k7 = kp[7], k8 = kp[8];

    // halos via intra-half-warp shuffles
    float la_ = __shfl_up_sync(0xffffffffu, R[0].w, 1);
    float ra_ = __shfl_down_sync(0xffffffffu, R[0].x, 1);
    float lb_ = __shfl_up_sync(0xffffffffu, R[1].w, 1);
    float rb_ = __shfl_down_sync(0xffffffffu, R[1].x, 1);
    float la = lok ? la_ : 0.f, ra = rok ? ra_ : 0.f;
    float lb = lok ? lb_ : 0.f, rb = rok ? rb_ : 0.f;

    float* op = out + plane * HW + y0 * 56 + xc;

    #pragma unroll
    for (int r = 0; r < 7; r++) {
        const float4 ca = R[r], cb = R[r + 1], cc = R[r + 2];
        const float lc_ = __shfl_up_sync(0xffffffffu, cc.w, 1);
        const float rc_ = __shfl_down_sync(0xffffffffu, cc.x, 1);
        const float lc = lok ? lc_ : 0.f;
        const float rc = rok ? rc_ : 0.f;

        float4 acc;
        acc.x = k0 * la;
        acc.x = fmaf(k1, ca.x, acc.x); acc.x = fmaf(k2, ca.y, acc.x);
        acc.x = fmaf(k3, lb,   acc.x); acc.x = fmaf(k4, cb.x, acc.x);
        acc.x = fmaf(k5, cb.y, acc.x); acc.x = fmaf(k6, lc,   acc.x);
        acc.x = fmaf(k7, cc.x, acc.x); acc.x = fmaf(k8, cc.y, acc.x);

        acc.y = k0 * ca.x;
        acc.y = fmaf(k1, ca.y, acc.y); acc.y = fmaf(k2, ca.z, acc.y);
        acc.y = fmaf(k3, cb.x, acc.y); acc.y = fmaf(k4, cb.y, acc.y);
        acc.y = fmaf(k5, cb.z, acc.y); acc.y = fmaf(k6, cc.x, acc.y);
        acc.y = fmaf(k7, cc.y, acc.y); acc.y = fmaf(k8, cc.z, acc.y);

        acc.z = k0 * ca.y;
        acc.z = fmaf(k1, ca.z, acc.z); acc.z = fmaf(k2, ca.w, acc.z);
        acc.z = fmaf(k3, cb.y, acc.z); acc.z = fmaf(k4, cb.z, acc.z);
        acc.z = fmaf(k5, cb.w, acc.z); acc.z = fmaf(k6, cc.y, acc.z);
        acc.z = fmaf(k7, cc.z, acc.z); acc.z = fmaf(k8, cc.w, acc.z);

        acc.w = k0 * ca.z;
        acc.w = fmaf(k1, ca.w, acc.w); acc.w = fmaf(k2, ra,   acc.w);
        acc.w = fmaf(k3, cb.z, acc.w); acc.w = fmaf(k4, cb.w, acc.w);
        acc.w = fmaf(k5, rb,   acc.w); acc.w = fmaf(k6, cc.z, acc.w);
        acc.w = fmaf(k7, cc.w, acc.w); acc.w = fmaf(k8, rc,   acc.w);

        if (act) __stcs(reinterpret_cast<float4*>(op + r * 56), acc);

        la = lb; ra = rb;
        lb = lc; rb = rc;
    }
}

extern "C" void kernel_launch(void* const* d_in, const int* in_sizes, int n_in,
                              void* d_out, int out_size) {
    const float* x  = (const float*)d_in[0];   // [32,256,56,56]
    const float* Wk = (const float*)d_in[1];   // [2304,256]
    const float* bk = (const float*)d_in[2];   // [2304]
    float* out = (float*)d_out;

    pool_kernel<<<2048, 256>>>(x);

    // PDL secondary launch: may begin while pool is draining; device code gates
    // the pooled-dependent phase via cudaGridDependencySynchronize().
    cudaLaunchConfig_t cfg = {};
    cfg.gridDim  = dim3(4096, 1, 1);
    cfg.blockDim = dim3(256, 1, 1);
    cfg.dynamicSmemBytes = 0;
    cudaLaunchAttribute attrs[1];
    attrs[0].id = cudaLaunchAttributeProgrammaticStreamSerialization;
    attrs[0].val.programmaticStreamSerializationAllowed = 1;
    cfg.attrs = attrs;
    cfg.numAttrs = 1;
    cudaLaunchKernelEx(&cfg, kconv_kernel, x, Wk, bk, out);
}

// round 12
// speedup vs baseline: 1.1981x; 1.1981x over previous
#include <cuda_runtime.h>

#define HW 3136

__device__ float g_pooled[32 * 256];

// ---------------- K1: global average pool (4 planes / block, 8-deep load batches) ----------------
__global__ void __launch_bounds__(256) pool_kernel(const float* __restrict__ x) {
    const int plane0 = blockIdx.x * 4;
    const float4* xp = reinterpret_cast<const float4*>(x + (size_t)plane0 * HW);
    const int tid = threadIdx.x;
    float s0 = 0.f, s1 = 0.f, s2 = 0.f, s3 = 0.f;

    {
        float4 a0 = xp[tid],        b0 = xp[tid + 784],
               c0 = xp[tid + 1568], d0 = xp[tid + 2352];
        float4 a1 = xp[tid + 256],  b1 = xp[tid + 1040],
               c1 = xp[tid + 1824], d1 = xp[tid + 2608];
        s0 = (a0.x + a0.y) + (a0.z + a0.w) + (a1.x + a1.y) + (a1.z + a1.w);
        s1 = (b0.x + b0.y) + (b0.z + b0.w) + (b1.x + b1.y) + (b1.z + b1.w);
        s2 = (c0.x + c0.y) + (c0.z + c0.w) + (c1.x + c1.y) + (c1.z + c1.w);
        s3 = (d0.x + d0.y) + (d0.z + d0.w) + (d1.x + d1.y) + (d1.z + d1.w);
    }
    {
        float4 a = xp[tid + 512], b = xp[tid + 1296],
               c = xp[tid + 2080], d = xp[tid + 2864];
        s0 += (a.x + a.y) + (a.z + a.w);
        s1 += (b.x + b.y) + (b.z + b.w);
        s2 += (c.x + c.y) + (c.z + c.w);
        s3 += (d.x + d.y) + (d.z + d.w);
    }
    if (tid < 16) {
        float4 a = xp[tid + 768], b = xp[tid + 1552],
               c = xp[tid + 2336], d = xp[tid + 3120];
        s0 += (a.x + a.y) + (a.z + a.w);
        s1 += (b.x + b.y) + (b.z + b.w);
        s2 += (c.x + c.y) + (c.z + c.w);
        s3 += (d.x + d.y) + (d.z + d.w);
    }

    #pragma unroll
    for (int o = 16; o; o >>= 1) {
        s0 += __shfl_xor_sync(0xffffffffu, s0, o);
        s1 += __shfl_xor_sync(0xffffffffu, s1, o);
        s2 += __shfl_xor_sync(0xffffffffu, s2, o);
        s3 += __shfl_xor_sync(0xffffffffu, s3, o);
    }
    __shared__ float sh[8][4];
    if ((tid & 31) == 0) {
        const int w = tid >> 5;
        sh[w][0] = s0; sh[w][1] = s1; sh[w][2] = s2; sh[w][3] = s3;
    }
    __syncthreads();
    if (tid < 32) {
        const int pl = tid & 3;
        const int w  = tid >> 2;
        float v = (w < 8) ? sh[w][pl] : 0.f;
        v += __shfl_xor_sync(0xffffffffu, v, 16);
        v += __shfl_xor_sync(0xffffffffu, v, 8);
        v += __shfl_xor_sync(0xffffffffu, v, 4);
        if (w == 0) g_pooled[plane0 + pl] = v * (1.0f / 3136.f);
    }
}

// ---------------- K2: kgen + depthwise 3x3; 6-deep rolling row window ----------------
// Reverse plane order (L2 recency vs pool). W[j%6] holds global row y0-1+j.
// 6 rows hoisted above kgen; rows 6..8 prefetched in-loop at distance 4 iters.
__global__ void __launch_bounds__(256, 5) kconv_kernel(const float* __restrict__ x,
                                                       const float* __restrict__ Wk,
                                                       const float* __restrict__ bk,
                                                       float* __restrict__ out)
{
    __shared__ float psh[256];
    __shared__ float kern_s[18];

    const int gid  = 4095 - blockIdx.x;
    const int b    = gid >> 7;
    const int pair = gid & 127;
    const int tid  = threadIdx.x;
    const int warp = tid >> 5, lane = tid & 31;
    const int c0   = pair * 2;

    // conv geometry: half-warp = (plane, row-group); cgp = lane&15
    const int grp = (warp << 1) | (lane >> 4);
    const int pl  = grp & 1;
    const int rg  = grp >> 1;
    const int cgp = lane & 15;
    const bool act = cgp < 14;
    const int xc = cgp * 4;
    const int y0 = rg * 7;
    const bool lok = act && (cgp > 0);
    const bool rok = act && (cgp < 13);

    const size_t plane = (size_t)b * 256 + c0 + pl;
    const float* xp = x + plane * HW + xc;

    // hoisted: first 6 window rows (global rows y0-1 .. y0+4)
    float4 W[6];
    const float4 z4 = make_float4(0.f, 0.f, 0.f, 0.f);
    W[0] = (act && rg > 0) ? __ldg(reinterpret_cast<const float4*>(xp + (y0 - 1) * 56)) : z4;
    #pragma unroll
    for (int j = 1; j < 6; j++)
        W[j] = act ? __ldg(reinterpret_cast<const float4*>(xp + (y0 - 1 + j) * 56)) : z4;

    // kgen: 18 rows over 8 warps (hidden behind the outstanding loads)
    psh[tid] = g_pooled[b * 256 + tid];
    __syncthreads();

    #pragma unroll
    for (int sl = 0; sl < 3; sl++) {
        if (sl == 2 && warp >= 2) break;
        const int r = (sl < 2) ? (2 * warp + sl) : (16 + warp);
        const int o = c0 * 9 + r;
        const float* wr = Wk + (size_t)o * 256;
        float a = 0.f;
        #pragma unroll
        for (int i = 0; i < 8; i++)
            a = fmaf(__ldg(wr + lane + 32 * i), psh[lane + 32 * i], a);
        #pragma unroll
        for (int off = 16; off; off >>= 1) a += __shfl_xor_sync(0xffffffffu, a, off);
        if (lane == 0) kern_s[r] = fmaxf(a + __ldg(bk + o), 0.f);
    }
    __syncthreads();

    const float* kp = kern_s + pl * 9;
    const float k0 = kp[0], k1 = kp[1], k2 = kp[2];
    const float k3 = kp[3], k4 = kp[4], k5 = kp[5];
    const float k6 = kp[6], k7 = kp[7], k8 = kp[8];

    // halos for first two window rows
    float la_ = __shfl_up_sync(0xffffffffu, W[0].w, 1);
    float ra_ = __shfl_down_sync(0xffffffffu, W[0].x, 1);
    float lb_ = __shfl_up_sync(0xffffffffu, W[1].w, 1);
    float rb_ = __shfl_down_sync(0xffffffffu, W[1].x, 1);
    float la = lok ? la_ : 0.f, ra = rok ? ra_ : 0.f;
    float lb = lok ? lb_ : 0.f, rb = rok ? rb_ : 0.f;

    float* op = out + plane * HW + y0 * 56 + xc;

    #pragma unroll
    for (int r = 0; r < 7; r++) {
        const float4 ca = W[r % 6], cb = W[(r + 1) % 6], cc = W[(r + 2) % 6];

        // prefetch global row y0-1+(r+6) into the slot ca just vacated
        if (r < 2) {
            W[r % 6] = act ? __ldg(reinterpret_cast<const float4*>(xp + (y0 + 5 + r) * 56)) : z4;
        } else if (r == 2) {
            W[2] = (act && rg < 7) ? __ldg(reinterpret_cast<const float4*>(xp + (y0 + 7) * 56)) : z4;
        }

        const float lc_ = __shfl_up_sync(0xffffffffu, cc.w, 1);
        const float rc_ = __shfl_down_sync(0xffffffffu, cc.x, 1);
        const float lc = lok ? lc_ : 0.f;
        const float rc = rok ? rc_ : 0.f;

        float4 acc;
        acc.x = k0 * la;
        acc.x = fmaf(k1, ca.x, acc.x); acc.x = fmaf(k2, ca.y, acc.x);
        acc.x = fmaf(k3, lb,   acc.x); acc.x = fmaf(k4, cb.x, acc.x);
        acc.x = fmaf(k5, cb.y, acc.x); acc.x = fmaf(k6, lc,   acc.x);
        acc.x = fmaf(k7, cc.x, acc.x); acc.x = fmaf(k8, cc.y, acc.x);

        acc.y = k0 * ca.x;
        acc.y = fmaf(k1, ca.y, acc.y); acc.y = fmaf(k2, ca.z, acc.y);
        acc.y = fmaf(k3, cb.x, acc.y); acc.y = fmaf(k4, cb.y, acc.y);
        acc.y = fmaf(k5, cb.z, acc.y); acc.y = fmaf(k6, cc.x, acc.y);
        acc.y = fmaf(k7, cc.y, acc.y); acc.y = fmaf(k8, cc.z, acc.y);

        acc.z = k0 * ca.y;
        acc.z = fmaf(k1, ca.z, acc.z); acc.z = fmaf(k2, ca.w, acc.z);
        acc.z = fmaf(k3, cb.y, acc.z); acc.z = fmaf(k4, cb.z, acc.z);
        acc.z = fmaf(k5, cb.w, acc.z); acc.z = fmaf(k6, cc.y, acc.z);
        acc.z = fmaf(k7, cc.z, acc.z); acc.z = fmaf(k8, cc.w, acc.z);

        acc.w = k0 * ca.z;
        acc.w = fmaf(k1, ca.w, acc.w); acc.w = fmaf(k2, ra,   acc.w);
        acc.w = fmaf(k3, cb.z, acc.w); acc.w = fmaf(k4, cb.w, acc.w);
        acc.w = fmaf(k5, rb,   acc.w); acc.w = fmaf(k6, cc.z, acc.w);
        acc.w = fmaf(k7, cc.w, acc.w); acc.w = fmaf(k8, rc,   acc.w);

        if (act) __stcs(reinterpret_cast<float4*>(op + r * 56), acc);

        la = lb; ra = rb;
        lb = lc; rb = rc;
    }
}

extern "C" void kernel_launch(void* const* d_in, const int* in_sizes, int n_in,
                              void* d_out, int out_size) {
    const float* x  = (const float*)d_in[0];   // [32,256,56,56]
    const float* Wk = (const float*)d_in[1];   // [2304,256]
    const float* bk = (const float*)d_in[2];   // [2304]
    float* out = (float*)d_out;

    pool_kernel<<<2048, 256>>>(x);
    kconv_kernel<<<4096, 256>>>(x, Wk, bk, out);
}